// round 7
// baseline (speedup 1.0000x reference)
#include <cuda_runtime.h>
#include <float.h>

#define ROW_LEN 4096
#define THREADS 256
#define V4 4                               // 256 * 4 * 4 = 4096 floats/row
#define NWARPS (THREADS / 32)              // 8

__global__ __launch_bounds__(THREADS, 8)
void masked_softmax_kernel(const float* __restrict__ X,
                           const int* __restrict__ N,
                           float* __restrict__ out) {
    const int row = blockIdx.x;
    const int tid = threadIdx.x;
    const int lane = tid & 31;
    const int wid = tid >> 5;

    const float4* __restrict__ xrow =
        reinterpret_cast<const float4*>(X + (size_t)row * ROW_LEN);
    float4* __restrict__ orow =
        reinterpret_cast<float4*>(out + (size_t)row * ROW_LEN);

    const int n = N[row];  // valid length in [1, ROW_LEN]

    __shared__ float red_m[NWARPS];
    __shared__ float red_s[NWARPS];

    // ---- Load ONLY the valid prefix (predicated-off LDGs = no traffic) ----
    float4 v[V4];
#pragma unroll
    for (int i = 0; i < V4; i++) {
        const int base = (tid + i * THREADS) * 4;
        if (base < n) v[i] = __ldcs(&xrow[tid + i * THREADS]);
    }

    // ---- EARLY zero-stores for fully-invalid groups: this store traffic
    //      flows while loads are in flight and during the reduction window ----
    const float4 z4 = make_float4(0.0f, 0.0f, 0.0f, 0.0f);
#pragma unroll
    for (int i = 0; i < V4; i++) {
        const int base = (tid + i * THREADS) * 4;
        if (base >= n) __stcs(&orow[tid + i * THREADS], z4);
    }

    // ---- Per-thread masked max (only valid groups) ----
    float m_local = -FLT_MAX;
#pragma unroll
    for (int i = 0; i < V4; i++) {
        const int rem = n - (tid + i * THREADS) * 4;
        const float* f = reinterpret_cast<const float*>(&v[i]);
        if (rem > 0) {
#pragma unroll
            for (int j = 0; j < 4; j++)
                if (j < rem) m_local = fmaxf(m_local, f[j]);
        }
    }

    // ---- exp(x - m_local) in place + masked local sum (valid groups only) ----
    float s = 0.0f;
#pragma unroll
    for (int i = 0; i < V4; i++) {
        const int rem = n - (tid + i * THREADS) * 4;
        float* f = reinterpret_cast<float*>(&v[i]);
        if (rem > 0) {
#pragma unroll
            for (int j = 0; j < 4; j++) {
                const float ev = (j < rem) ? __expf(f[j] - m_local) : 0.0f;
                f[j] = ev;
                s += ev;
            }
        }
    }

    // ---- Online (m,s) warp reduction (m_local preserved) ----
    float m = m_local;
#pragma unroll
    for (int o = 16; o > 0; o >>= 1) {
        const float mo = __shfl_xor_sync(0xFFFFFFFFu, m, o);
        const float so = __shfl_xor_sync(0xFFFFFFFFu, s, o);
        const float mn = fmaxf(m, mo);
        s = s * __expf(m - mn) + so * __expf(mo - mn);
        m = mn;
    }
    if (lane == 0) { red_m[wid] = m; red_s[wid] = s; }
    __syncthreads();  // the ONLY barrier

    // ---- Every thread redundantly merges the 8 warp partials (no 2nd sync) ----
    float M = red_m[0];
    float S = red_s[0];
#pragma unroll
    for (int w = 1; w < NWARPS; w++) {
        const float mo = red_m[w];
        const float so = red_s[w];
        const float mn = fmaxf(M, mo);
        S = S * __expf(M - mn) + so * __expf(mo - mn);
        M = mn;
    }

    // ---- Rescale with thread-local max; store valid-prefix groups only ----
    const float scale = __fdividef(__expf(m_local - M), S);

#pragma unroll
    for (int i = 0; i < V4; i++) {
        const int base = (tid + i * THREADS) * 4;
        if (base < n) {
            const float* f = reinterpret_cast<const float*>(&v[i]);
            float4 o4;
            o4.x = f[0] * scale;
            o4.y = f[1] * scale;
            o4.z = f[2] * scale;
            o4.w = f[3] * scale;
            __stcs(&orow[tid + i * THREADS], o4);
        }
    }
}

extern "C" void kernel_launch(void* const* d_in, const int* in_sizes, int n_in,
                              void* d_out, int out_size) {
    const float* X = (const float*)d_in[0];
    const int* N = (const int*)d_in[1];
    float* out = (float*)d_out;

    const int B = in_sizes[1];  // one int per row
    masked_softmax_kernel<<<B, THREADS>>>(X, N, out);
}